// round 1
// baseline (speedup 1.0000x reference)
#include <cuda_runtime.h>
#include <cstdint>

#define NQ   512
#define SS   2048
#define DD   128
#define TOPK 32
#define CLS  1000

// scratch for attention summary (per rules: no cudaMalloc; __device__ global)
__device__ float g_summary[NQ * DD];

__device__ __forceinline__ float warp_sum(float v) {
    #pragma unroll
    for (int o = 16; o > 0; o >>= 1) v += __shfl_xor_sync(0xffffffffu, v, o);
    return v;
}

__global__ __launch_bounds__(256, 4) void attn_topk_kernel(
    const float* __restrict__ q,
    const float* __restrict__ Kmat,
    const float* __restrict__ Vmat,
    float* __restrict__ weights_out)
{
    const int n    = blockIdx.x;
    const int tid  = threadIdx.x;
    const int warp = tid >> 5;
    const int lane = tid & 31;

    __shared__ float logits[SS];
    __shared__ float s_topv[TOPK];
    __shared__ int   s_topi[TOPK];
    __shared__ float s_w[TOPK];
    __shared__ float red_v[8];
    __shared__ int   red_i[8];

    const float NEG_INF = __int_as_float(0xff800000);
    const float scale   = 0.08838834764831845f; // 1/sqrt(128)

    // q row: one float4 per lane (d = lane*4 .. lane*4+3), constant across rows
    const float4 qv = reinterpret_cast<const float4*>(q + (size_t)n * DD)[lane];
    const float4* __restrict__ K4 =
        reinterpret_cast<const float4*>(Kmat + (size_t)n * SS * DD);

    // ---- Phase A: logits.  warp-per-row, 4 independent rows in flight ----
    for (int s0 = warp * 4; s0 < SS; s0 += 32) {
        float4 k0 = K4[(size_t)(s0 + 0) * 32 + lane];
        float4 k1 = K4[(size_t)(s0 + 1) * 32 + lane];
        float4 k2 = K4[(size_t)(s0 + 2) * 32 + lane];
        float4 k3 = K4[(size_t)(s0 + 3) * 32 + lane];
        float p0 = qv.x*k0.x + qv.y*k0.y + qv.z*k0.z + qv.w*k0.w;
        float p1 = qv.x*k1.x + qv.y*k1.y + qv.z*k1.z + qv.w*k1.w;
        float p2 = qv.x*k2.x + qv.y*k2.y + qv.z*k2.z + qv.w*k2.w;
        float p3 = qv.x*k3.x + qv.y*k3.y + qv.z*k3.z + qv.w*k3.w;
        p0 = warp_sum(p0); p1 = warp_sum(p1);
        p2 = warp_sum(p2); p3 = warp_sum(p3);
        if (lane == 0) {
            logits[s0 + 0] = p0 * scale;
            logits[s0 + 1] = p1 * scale;
            logits[s0 + 2] = p2 * scale;
            logits[s0 + 3] = p3 * scale;
        }
    }

    // zero the weights output row while logits settle (global stores, ordered
    // vs. the later scatter by the __syncthreads barriers below)
    {
        float4 z = make_float4(0.f, 0.f, 0.f, 0.f);
        float4* w4 = reinterpret_cast<float4*>(weights_out + (size_t)n * SS);
        #pragma unroll
        for (int i = tid; i < SS / 4; i += 256) w4[i] = z;
    }
    __syncthreads();

    // ---- Phase B: top-32 by iterative argmax (tie -> lowest index) ----
    for (int k = 0; k < TOPK; k++) {
        float best = NEG_INF;
        int   bidx = SS;
        for (int s = tid; s < SS; s += 256) {
            float v = logits[s];
            if (v > best) { best = v; bidx = s; }
        }
        #pragma unroll
        for (int o = 16; o > 0; o >>= 1) {
            float ov = __shfl_xor_sync(0xffffffffu, best, o);
            int   oi = __shfl_xor_sync(0xffffffffu, bidx, o);
            if (ov > best || (ov == best && oi < bidx)) { best = ov; bidx = oi; }
        }
        if (lane == 0) { red_v[warp] = best; red_i[warp] = bidx; }
        __syncthreads();
        if (warp == 0) {
            float b = (lane < 8) ? red_v[lane] : NEG_INF;
            int   bi = (lane < 8) ? red_i[lane] : SS;
            #pragma unroll
            for (int o = 4; o > 0; o >>= 1) {
                float ov = __shfl_xor_sync(0xffffffffu, b, o);
                int   oi = __shfl_xor_sync(0xffffffffu, bi, o);
                if (ov > b || (ov == b && oi < bi)) { b = ov; bi = oi; }
            }
            if (lane == 0) {
                s_topv[k] = b;
                s_topi[k] = bi;
                logits[bi] = NEG_INF;  // remove from further passes
            }
        }
        __syncthreads();
    }

    // ---- Phase C: softmax over the 32 kept values (warp 0) ----
    if (warp == 0) {
        float v = s_topv[lane];          // TOPK == 32 == warp size
        float m = s_topv[0];             // first extracted max
        float e = expf(v - m);
        float denom = warp_sum(e);
        s_w[lane] = e / denom;
    }
    __syncthreads();

    // ---- Phase D: summary[n, d] = sum_k w[k] * V[n, idx[k], d] ----
    if (tid < DD) {
        float acc = 0.f;
        #pragma unroll
        for (int i = 0; i < TOPK; i++) {
            acc += s_w[i] * Vmat[((size_t)n * SS + s_topi[i]) * DD + tid];
        }
        g_summary[n * DD + tid] = acc;
    }

    // ---- Phase E: scatter weights ----
    if (tid < TOPK) {
        weights_out[(size_t)n * SS + s_topi[tid]] = s_w[tid];
    }
}

// out[n, c] = sum_d g_summary[n, d] * W[c, d] + bias[c]
// 64x64 tile, 16x16 threads, 4x4 micro-tile, K chunked by 32.
__global__ __launch_bounds__(256) void readout_gemm(
    const float* __restrict__ W,     // [C, 128]
    const float* __restrict__ bias,  // [C]
    float* __restrict__ out,         // [NQ, C]
    int C)
{
    const int tx = threadIdx.x & 15;
    const int ty = threadIdx.x >> 4;
    const int cTile = blockIdx.x * 64;
    const int nTile = blockIdx.y * 64;

    __shared__ float As[32][65];  // [kk][n_local]
    __shared__ float Bs[32][65];  // [kk][c_local]

    float acc[4][4];
    #pragma unroll
    for (int i = 0; i < 4; i++)
        #pragma unroll
        for (int j = 0; j < 4; j++) acc[i][j] = 0.f;

    for (int k0 = 0; k0 < DD; k0 += 32) {
        #pragma unroll
        for (int e = 0; e < 8; e++) {
            int linear = threadIdx.x + e * 256;  // 0..2047
            int rr = linear >> 5;                // 0..63
            int kk = linear & 31;                // 0..31
            As[kk][rr] = g_summary[(nTile + rr) * DD + k0 + kk];
            int cg = cTile + rr;
            Bs[kk][rr] = (cg < C) ? W[(size_t)cg * DD + k0 + kk] : 0.f;
        }
        __syncthreads();
        #pragma unroll
        for (int kk = 0; kk < 32; kk++) {
            float a[4], b[4];
            #pragma unroll
            for (int i = 0; i < 4; i++) a[i] = As[kk][ty * 4 + i];
            #pragma unroll
            for (int j = 0; j < 4; j++) b[j] = Bs[kk][tx * 4 + j];
            #pragma unroll
            for (int i = 0; i < 4; i++)
                #pragma unroll
                for (int j = 0; j < 4; j++)
                    acc[i][j] += a[i] * b[j];
        }
        __syncthreads();
    }

    #pragma unroll
    for (int i = 0; i < 4; i++) {
        int nn = nTile + ty * 4 + i;
        #pragma unroll
        for (int j = 0; j < 4; j++) {
            int cg = cTile + tx * 4 + j;
            if (cg < C) out[(size_t)nn * C + cg] = acc[i][j] + bias[cg];
        }
    }
}

extern "C" void kernel_launch(void* const* d_in, const int* in_sizes, int n_in,
                              void* d_out, int out_size) {
    const float* q     = (const float*)d_in[0];
    const float* Kmat  = (const float*)d_in[1];
    const float* Vmat  = (const float*)d_in[2];
    const float* W_cls = (const float*)d_in[3];
    const float* b_cls = (const float*)d_in[4];
    const float* W_rec = (const float*)d_in[5];
    const float* b_rec = (const float*)d_in[6];

    float* out = (float*)d_out;
    float* cls = out;                               // [512, 1000]
    float* rec = out + (size_t)NQ * CLS;            // [512, 128]
    float* wts = rec + (size_t)NQ * DD;             // [512, 2048]

    attn_topk_kernel<<<NQ, 256>>>(q, Kmat, Vmat, wts);

    readout_gemm<<<dim3((CLS + 63) / 64, NQ / 64), 256>>>(W_cls, b_cls, cls, CLS);
    readout_gemm<<<dim3((DD  + 63) / 64, NQ / 64), 256>>>(W_rec, b_rec, rec, DD);
}